// round 3
// baseline (speedup 1.0000x reference)
#include <cuda_runtime.h>
#include <math.h>

// Problem constants
#define BB 1024
#define NN 256
#define DD 256
#define MM 768          // 3*D
#define NEGV -1e10f

// Scratch (device globals: no allocation allowed)
__device__ float g_O[BB * MM];    // attention output (pre-fc), per batch
__device__ float g_Y[BB * MM];    // O @ fc_w.T + q
__device__ float g_H[BB * MM];    // LayerNorm(Y)
__device__ float g_X1[BB * MM];   // relu([H, src] @ W1.T)

// ---------------------------------------------------------------------------
// Kernel 1: streaming single-query attention with online softmax.
// One CTA per batch, 192 threads = 6 warps. Warp w owns element chunk
// [128w, 128w+128) of the concatenated key vector [seq | seq_e | seq_t].
// Each lane owns one float4. Per round of 8 keys: coalesced float4 loads,
// warp-level dot-product partials, cross-warp smem reduce, online-softmax
// state update by warp 0, then accumulator update from the register-resident
// key fragments. Each key element touches DRAM exactly once.
// NOTE softmax shift-invariance: sq (the query logit) is constant along the
// softmax axis and masked entries are set to exactly NEG (not added), so wq
// cancels and is never read.
// ---------------------------------------------------------------------------
__global__ __launch_bounds__(192) void attn_kernel(
    const float* __restrict__ seq,
    const float* __restrict__ seq_t,
    const float* __restrict__ seq_e,
    const int* __restrict__ mask,          // 32-bit; nonzero == True (works for int32 AND float32 encodings)
    const float* __restrict__ shared_attn,
    float* __restrict__ attn_out)          // d_out + B*D
{
    const int b    = blockIdx.x;
    const int tid  = threadIdx.x;
    const int w    = tid >> 5;
    const int lane = tid & 31;
    const int e0   = 128 * w + 4 * lane;      // element index in [0,768)

    // which tensor does this chunk live in: [seq | seq_e | seq_t]
    const int tsel = e0 >> 8;                 // 0:seq 1:seq_e 2:seq_t
    const int off  = e0 & 255;
    const float* kbase = (tsel == 0) ? seq : (tsel == 1 ? seq_e : seq_t);
    const float* krow0 = kbase + (size_t)b * NN * DD + off;   // row stride DD

    // wk lives at shared_attn[M : 2M]
    const float4 wk4 = *reinterpret_cast<const float4*>(shared_attn + MM + e0);

    __shared__ float s_part[6][8];
    __shared__ float s_w[8];
    __shared__ float s_scale;
    __shared__ float s_m, s_Z;
    __shared__ float s_sk[NN];

    if (tid == 0) { s_m = -INFINITY; s_Z = 0.f; }
    __syncthreads();

    float ox = 0.f, oy = 0.f, oz = 0.f, ow = 0.f;
    const int* mrow = mask + (size_t)b * NN;

    for (int n0 = 0; n0 < NN; n0 += 8) {
        float4 kk[8];
#pragma unroll
        for (int j = 0; j < 8; j++)
            kk[j] = *reinterpret_cast<const float4*>(krow0 + (size_t)(n0 + j) * DD);

        float p[8];
#pragma unroll
        for (int j = 0; j < 8; j++)
            p[j] = kk[j].x * wk4.x + kk[j].y * wk4.y + kk[j].z * wk4.z + kk[j].w * wk4.w;

        // butterfly reduce each of the 8 partials across the warp
#pragma unroll
        for (int s = 16; s; s >>= 1) {
#pragma unroll
            for (int j = 0; j < 8; j++)
                p[j] += __shfl_xor_sync(0xffffffffu, p[j], s);
        }
        if (lane < 8) s_part[w][lane] = p[lane];
        __syncthreads();

        if (tid < 8) {
            const int j = tid;
            float sk = s_part[0][j] + s_part[1][j] + s_part[2][j] +
                       s_part[3][j] + s_part[4][j] + s_part[5][j];
            if (mrow[n0 + j] != 0) sk = NEGV;
            s_sk[n0 + j] = sk;
            // max over the 8 logits
            float mx = sk;
#pragma unroll
            for (int s = 4; s; s >>= 1)
                mx = fmaxf(mx, __shfl_xor_sync(0x000000ffu, mx, s));
            const float m_old = s_m;
            const float m_new = fmaxf(m_old, mx);
            const float scale = __expf(m_old - m_new);   // exp(-inf)=0 first round
            const float wgt   = __expf(sk - m_new);
            float ws = wgt;
#pragma unroll
            for (int s = 4; s; s >>= 1)
                ws += __shfl_xor_sync(0x000000ffu, ws, s);
            __syncwarp(0x000000ffu);
            s_w[j] = wgt;
            if (j == 0) {
                s_scale = scale;
                s_Z = s_Z * scale + ws;
                s_m = m_new;
            }
        }
        __syncthreads();

        const float sc = s_scale;
        ox *= sc; oy *= sc; oz *= sc; ow *= sc;
#pragma unroll
        for (int j = 0; j < 8; j++) {
            const float wj = s_w[j];
            ox += wj * kk[j].x;
            oy += wj * kk[j].y;
            oz += wj * kk[j].z;
            ow += wj * kk[j].w;
        }
    }

    const float mf  = s_m;
    const float inv = 1.f / s_Z;
    float4 of;
    of.x = ox * inv; of.y = oy * inv; of.z = oz * inv; of.w = ow * inv;
    *reinterpret_cast<float4*>(&g_O[(size_t)b * MM + e0]) = of;

    for (int i = tid; i < NN; i += 192)
        attn_out[(size_t)b * NN + i] = __expf(s_sk[i] - mf) * inv;
}

// ---------------------------------------------------------------------------
// Tiled SGEMM: C[m][n] = sum_k A[m][k] * W[n][k]   (both row-major, K contig)
// BM=BN=64, BK=16, 256 threads, 4x4 register tile per thread.
// Software-pipelined: global fragments for step i+1 are prefetched into
// registers before step i's compute, hiding DRAM/L2 latency behind FMAs.
// MODE 0: A=g_O, C=g_Y, epilogue += q (q=[src,0,src_t])
// MODE 1: A=[g_H | src] concat (K=1024), C=g_X1, epilogue relu
// MODE 2: A=g_X1, C=d_out (first B*D floats)
// ---------------------------------------------------------------------------
template<int MODE, int K, int NCOLS>
__global__ __launch_bounds__(256) void gemm_kernel(
    const float* __restrict__ W,
    float* __restrict__ Cout,               // used by MODE 2 only
    const float* __restrict__ src,
    const float* __restrict__ src_t)
{
    constexpr int BM = 64, BN = 64, BK = 16;
    __shared__ float As[BK][BM + 4];
    __shared__ float Ws[BK][BN + 4];

    const int tid = threadIdx.x;
    const int m0 = blockIdx.x * BM;
    const int n0 = blockIdx.y * BN;
    const int tm = tid & 15;        // 0..15
    const int tn = tid >> 4;        // 0..15
    const int l_row = tid >> 2;     // 0..63
    const int l_k0  = (tid & 3) * 4;

    const float* A;
    float* C;
    if (MODE == 0) { A = g_O;  C = g_Y;  }
    else if (MODE == 1) { A = g_H;  C = g_X1; }
    else { A = g_X1; C = Cout; }

    const int gm = m0 + l_row;
    const int gn = n0 + l_row;

    // fragment loaders (gk = k0 + l_k0)
    auto loadA = [&](int k0) -> float4 {
        const int gk = k0 + l_k0;
        if (MODE == 1) {
            if (gk < MM) return *reinterpret_cast<const float4*>(A + (size_t)gm * MM + gk);
            return *reinterpret_cast<const float4*>(src + (size_t)gm * DD + (gk - MM));
        }
        return *reinterpret_cast<const float4*>(A + (size_t)gm * K + gk);
    };
    auto loadW = [&](int k0) -> float4 {
        return *reinterpret_cast<const float4*>(W + (size_t)gn * K + (k0 + l_k0));
    };

    float acc[4][4] = {};

    float4 av = loadA(0);
    float4 wv = loadW(0);

    for (int k0 = 0; k0 < K; k0 += BK) {
        __syncthreads();            // previous step done reading smem
        As[l_k0 + 0][l_row] = av.x; As[l_k0 + 1][l_row] = av.y;
        As[l_k0 + 2][l_row] = av.z; As[l_k0 + 3][l_row] = av.w;
        Ws[l_k0 + 0][l_row] = wv.x; Ws[l_k0 + 1][l_row] = wv.y;
        Ws[l_k0 + 2][l_row] = wv.z; Ws[l_k0 + 3][l_row] = wv.w;
        __syncthreads();

        // prefetch next step's fragments (latency hidden under compute below)
        if (k0 + BK < K) { av = loadA(k0 + BK); wv = loadW(k0 + BK); }

#pragma unroll
        for (int k = 0; k < BK; k++) {
            const float4 a4 = *reinterpret_cast<const float4*>(&As[k][tm * 4]);
            const float4 w4 = *reinterpret_cast<const float4*>(&Ws[k][tn * 4]);
            acc[0][0] += a4.x * w4.x; acc[0][1] += a4.x * w4.y;
            acc[0][2] += a4.x * w4.z; acc[0][3] += a4.x * w4.w;
            acc[1][0] += a4.y * w4.x; acc[1][1] += a4.y * w4.y;
            acc[1][2] += a4.y * w4.z; acc[1][3] += a4.y * w4.w;
            acc[2][0] += a4.z * w4.x; acc[2][1] += a4.z * w4.y;
            acc[2][2] += a4.z * w4.z; acc[2][3] += a4.z * w4.w;
            acc[3][0] += a4.w * w4.x; acc[3][1] += a4.w * w4.y;
            acc[3][2] += a4.w * w4.z; acc[3][3] += a4.w * w4.w;
        }
    }

#pragma unroll
    for (int i = 0; i < 4; i++) {
        const int m = m0 + tm * 4 + i;
        const int c0 = n0 + tn * 4;
        float4 v;
        v.x = acc[i][0]; v.y = acc[i][1]; v.z = acc[i][2]; v.w = acc[i][3];
        if (MODE == 0) {
            // residual q = [src | 0 | src_t]; float4 chunks never straddle boundaries
            if (c0 < DD) {
                const float4 qv = *reinterpret_cast<const float4*>(src + (size_t)m * DD + c0);
                v.x += qv.x; v.y += qv.y; v.z += qv.z; v.w += qv.w;
            } else if (c0 >= 2 * DD) {
                const float4 qv = *reinterpret_cast<const float4*>(src_t + (size_t)m * DD + (c0 - 2 * DD));
                v.x += qv.x; v.y += qv.y; v.z += qv.z; v.w += qv.w;
            }
        } else if (MODE == 1) {
            v.x = fmaxf(v.x, 0.f); v.y = fmaxf(v.y, 0.f);
            v.z = fmaxf(v.z, 0.f); v.w = fmaxf(v.w, 0.f);
        }
        *reinterpret_cast<float4*>(&C[(size_t)m * NCOLS + c0]) = v;
    }
}

// ---------------------------------------------------------------------------
// LayerNorm over rows of g_Y -> g_H.  One CTA per batch, 256 threads,
// each thread owns 3 elements (t, t+256, t+512).
// ---------------------------------------------------------------------------
__global__ __launch_bounds__(256) void ln_kernel(
    const float* __restrict__ ln_w,
    const float* __restrict__ ln_b)
{
    const int b = blockIdx.x;
    const int t = threadIdx.x;
    const float* yr = g_Y + (size_t)b * MM;
    const float v0 = yr[t], v1 = yr[t + 256], v2 = yr[t + 512];

    float s = v0 + v1 + v2;
    float q = v0 * v0 + v1 * v1 + v2 * v2;
    __shared__ float sh[16];
#pragma unroll
    for (int o = 16; o; o >>= 1) {
        s += __shfl_xor_sync(0xffffffffu, s, o);
        q += __shfl_xor_sync(0xffffffffu, q, o);
    }
    const int wd = t >> 5, lane = t & 31;
    if (lane == 0) { sh[wd] = s; sh[8 + wd] = q; }
    __syncthreads();
    float st = 0.f, qt = 0.f;
#pragma unroll
    for (int i = 0; i < 8; i++) { st += sh[i]; qt += sh[8 + i]; }

    const float mu  = st * (1.f / 768.f);
    const float var = qt * (1.f / 768.f) - mu * mu;
    const float r   = rsqrtf(var + 1e-5f);
    float* hr = g_H + (size_t)b * MM;
    hr[t]       = (v0 - mu) * r * ln_w[t]       + ln_b[t];
    hr[t + 256] = (v1 - mu) * r * ln_w[t + 256] + ln_b[t + 256];
    hr[t + 512] = (v2 - mu) * r * ln_w[t + 512] + ln_b[t + 512];
}

// ---------------------------------------------------------------------------
extern "C" void kernel_launch(void* const* d_in, const int* in_sizes, int n_in,
                              void* d_out, int out_size)
{
    const float* src         = (const float*)d_in[0];
    const float* src_t       = (const float*)d_in[1];
    const float* seq         = (const float*)d_in[2];
    const float* seq_t       = (const float*)d_in[3];
    const float* seq_e       = (const float*)d_in[4];
    const int*   mask        = (const int*)d_in[5];     // bool promoted to 32-bit; nonzero test
    const float* shared_attn = (const float*)d_in[6];
    const float* fc_w        = (const float*)d_in[7];
    const float* ln_w        = (const float*)d_in[8];
    const float* ln_b        = (const float*)d_in[9];
    const float* w1          = (const float*)d_in[10];
    const float* w2          = (const float*)d_in[11];

    float* out      = (float*)d_out;          // (B, D) = first 262144 floats
    float* attn_out = out + (size_t)BB * DD;  // (B, N) = next 262144 floats

    // 1) attention (DRAM-bound pass over seq/seq_e/seq_t, once)
    attn_kernel<<<BB, 192>>>(seq, seq_t, seq_e, mask, shared_attn, attn_out);

    // 2) Y = O @ fc_w.T + q
    gemm_kernel<0, MM, MM><<<dim3(BB / 64, MM / 64), 256>>>(fc_w, nullptr, src, src_t);

    // 3) H = LN(Y) * ln_w + ln_b
    ln_kernel<<<BB, 256>>>(ln_w, ln_b);

    // 4) X1 = relu([H, src] @ W1.T)
    gemm_kernel<1, MM + DD, MM><<<dim3(BB / 64, MM / 64), 256>>>(w1, nullptr, src, src_t);

    // 5) out = X1 @ W2.T
    gemm_kernel<2, MM, DD><<<dim3(BB / 64, DD / 64), 256>>>(w2, out, src, src_t);
}

// round 6
// speedup vs baseline: 1.3763x; 1.3763x over previous
#include <cuda_runtime.h>
#include <math.h>
#include <stdint.h>

// Problem constants
#define BB 1024
#define NN 256
#define DD 256
#define MM 768          // 3*D
#define NEGV -1e10f

// Scratch (device globals: no allocation allowed)
__device__ float g_O[BB * MM];        // attention output (pre-fc)
__device__ float g_H[BB * MM];        // LayerNorm output
__device__ float g_X1[BB * MM];       // relu([H, src] @ W1.T)
__device__ float g_P[2 * BB * MM];    // split-K partial sums (reused by all GEMMs)

// ---------------------------------------------------------------------------
// tf32 helpers
// ---------------------------------------------------------------------------
__device__ __forceinline__ float to_tf32(float x) {
    uint32_t r;
    asm("cvt.rna.tf32.f32 %0, %1;" : "=r"(r) : "f"(x));
    return __uint_as_float(r);
}

__device__ __forceinline__ void mma_tf32(float* c, const uint32_t* a, const uint32_t* b) {
    asm volatile(
        "mma.sync.aligned.m16n8k8.row.col.f32.tf32.tf32.f32 "
        "{%0,%1,%2,%3}, {%4,%5,%6,%7}, {%8,%9}, {%0,%1,%2,%3};"
        : "+f"(c[0]), "+f"(c[1]), "+f"(c[2]), "+f"(c[3])
        : "r"(a[0]), "r"(a[1]), "r"(a[2]), "r"(a[3]), "r"(b[0]), "r"(b[1]));
}

// ---------------------------------------------------------------------------
// Kernel 1: streaming single-query attention with online softmax.
// One CTA per batch, 192 threads = 6 warps; warp w owns chunk [128w,128w+128)
// of the concatenated key [seq | seq_e | seq_t]. Each key element is read from
// DRAM exactly once (flash-style online softmax, key fragments in registers).
// sq/wq cancels by softmax shift invariance (mask SETS logits to NEG).
// ---------------------------------------------------------------------------
__global__ __launch_bounds__(192) void attn_kernel(
    const float* __restrict__ seq,
    const float* __restrict__ seq_t,
    const float* __restrict__ seq_e,
    const int* __restrict__ mask,          // 32-bit; nonzero == True
    const float* __restrict__ shared_attn,
    float* __restrict__ attn_out)          // d_out + B*D
{
    const int b    = blockIdx.x;
    const int tid  = threadIdx.x;
    const int w    = tid >> 5;
    const int lane = tid & 31;
    const int e0   = 128 * w + 4 * lane;      // element index in [0,768)

    const int tsel = e0 >> 8;                 // 0:seq 1:seq_e 2:seq_t
    const int off  = e0 & 255;
    const float* kbase = (tsel == 0) ? seq : (tsel == 1 ? seq_e : seq_t);
    const float* krow0 = kbase + (size_t)b * NN * DD + off;

    const float4 wk4 = *reinterpret_cast<const float4*>(shared_attn + MM + e0);

    __shared__ float s_part[6][8];
    __shared__ float s_w[8];
    __shared__ float s_scale;
    __shared__ float s_m, s_Z;
    __shared__ float s_sk[NN];

    if (tid == 0) { s_m = -INFINITY; s_Z = 0.f; }
    __syncthreads();

    float ox = 0.f, oy = 0.f, oz = 0.f, ow = 0.f;
    const int* mrow = mask + (size_t)b * NN;

    for (int n0 = 0; n0 < NN; n0 += 8) {
        float4 kk[8];
#pragma unroll
        for (int j = 0; j < 8; j++)
            kk[j] = *reinterpret_cast<const float4*>(krow0 + (size_t)(n0 + j) * DD);

        float p[8];
#pragma unroll
        for (int j = 0; j < 8; j++)
            p[j] = kk[j].x * wk4.x + kk[j].y * wk4.y + kk[j].z * wk4.z + kk[j].w * wk4.w;

#pragma unroll
        for (int s = 16; s; s >>= 1) {
#pragma unroll
            for (int j = 0; j < 8; j++)
                p[j] += __shfl_xor_sync(0xffffffffu, p[j], s);
        }
        if (lane < 8) s_part[w][lane] = p[lane];
        __syncthreads();

        if (tid < 8) {
            const int j = tid;
            float sk = s_part[0][j] + s_part[1][j] + s_part[2][j] +
                       s_part[3][j] + s_part[4][j] + s_part[5][j];
            if (mrow[n0 + j] != 0) sk = NEGV;
            s_sk[n0 + j] = sk;
            float mx = sk;
#pragma unroll
            for (int s = 4; s; s >>= 1)
                mx = fmaxf(mx, __shfl_xor_sync(0x000000ffu, mx, s));
            const float m_old = s_m;
            const float m_new = fmaxf(m_old, mx);
            const float scale = __expf(m_old - m_new);
            const float wgt   = __expf(sk - m_new);
            float ws = wgt;
#pragma unroll
            for (int s = 4; s; s >>= 1)
                ws += __shfl_xor_sync(0x000000ffu, ws, s);
            __syncwarp(0x000000ffu);
            s_w[j] = wgt;
            if (j == 0) {
                s_scale = scale;
                s_Z = s_Z * scale + ws;
                s_m = m_new;
            }
        }
        __syncthreads();

        const float sc = s_scale;
        ox *= sc; oy *= sc; oz *= sc; ow *= sc;
#pragma unroll
        for (int j = 0; j < 8; j++) {
            const float wj = s_w[j];
            ox += wj * kk[j].x;
            oy += wj * kk[j].y;
            oz += wj * kk[j].z;
            ow += wj * kk[j].w;
        }
    }

    const float mf  = s_m;
    const float inv = 1.f / s_Z;
    float4 of;
    of.x = ox * inv; of.y = oy * inv; of.z = oz * inv; of.w = ow * inv;
    *reinterpret_cast<float4*>(&g_O[(size_t)b * MM + e0]) = of;

    for (int i = tid; i < NN; i += 192)
        attn_out[(size_t)b * NN + i] = __expf(s_sk[i] - mf) * inv;
}

// ---------------------------------------------------------------------------
// Split-K tf32 tensor-core GEMM:
//   partial C[m][n] = sum_{k in slice z} A[m][k] * W[n][k]
// BM=BN=64, BK=16, 256 threads = 8 warps (2 along M x 4 along N), each warp
// computes a 32x16 tile via 2x2 mma.m16n8k8 per 8-wide k-chunk.
// Smem K-major with +8 pad -> stride 72 floats -> every fragment access
// pattern (8*tig+grp)%32 is bank-conflict-free. Double-buffered, one
// __syncthreads per BK step, register prefetch of next global fragments.
// Inputs rounded to tf32 (cvt.rna) at smem store; accumulate fp32.
// MODE 0: A=g_O            K=768,  S=2, NCOLS=768
// MODE 1: A=[g_H|src]      K=1024, S=2, NCOLS=768
// MODE 2: A=g_X1           K=768,  S=4, NCOLS=256
// ---------------------------------------------------------------------------
template<int MODE, int K, int S, int NCOLS>
__global__ __launch_bounds__(256) void gemm_kernel(
    const float* __restrict__ W,
    const float* __restrict__ src)
{
    constexpr int BM = 64, BN = 64, BK = 16;
    constexpr int KS = K / S;                  // K per slice
    constexpr int LDS = BM + 8;                // 72
    __shared__ float As[2][BK][LDS];           // As[buf][k][m]
    __shared__ float Ws[2][BK][LDS];           // Ws[buf][k][n] = W[n0+n][k]

    const int tid = threadIdx.x;
    const int m0 = blockIdx.x * BM;
    const int n0 = blockIdx.y * BN;
    const int z  = blockIdx.z;
    const int kbeg = z * KS;

    // staging-store mapping
    const int l_row = tid >> 2;      // 0..63
    const int l_k0  = (tid & 3) * 4; // 0,4,8,12

    // mma mapping
    const int ww   = tid >> 5;       // 0..7
    const int lane = tid & 31;
    const int wm   = ww & 1;         // 2 warps along M -> 32 rows each
    const int wn   = ww >> 1;        // 4 warps along N -> 16 cols each
    const int grp  = lane >> 2;      // 0..7
    const int tig  = lane & 3;       // 0..3

    const float* A = (MODE == 0) ? g_O : (MODE == 1) ? g_H : g_X1;
    float* P = g_P + (size_t)z * BB * NCOLS;

    const int gm = m0 + l_row;
    const int gn = n0 + l_row;

    auto loadA = [&](int k0) -> float4 {
        const int gk = k0 + l_k0;
        if (MODE == 1) {
            if (gk < MM) return *reinterpret_cast<const float4*>(A + (size_t)gm * MM + gk);
            return *reinterpret_cast<const float4*>(src + (size_t)gm * DD + (gk - MM));
        }
        return *reinterpret_cast<const float4*>(A + (size_t)gm * K + gk);
    };
    auto loadW = [&](int k0) -> float4 {
        return *reinterpret_cast<const float4*>(W + (size_t)gn * K + (k0 + l_k0));
    };

    float acc[2][2][4] = {};   // [mi][ni][c0..c3]

    float4 av = loadA(kbeg);
    float4 wv = loadW(kbeg);
    int buf = 0;

    for (int k0 = kbeg; k0 < kbeg + KS; k0 += BK) {
        As[buf][l_k0 + 0][l_row] = to_tf32(av.x);
        As[buf][l_k0 + 1][l_row] = to_tf32(av.y);
        As[buf][l_k0 + 2][l_row] = to_tf32(av.z);
        As[buf][l_k0 + 3][l_row] = to_tf32(av.w);
        Ws[buf][l_k0 + 0][l_row] = to_tf32(wv.x);
        Ws[buf][l_k0 + 1][l_row] = to_tf32(wv.y);
        Ws[buf][l_k0 + 2][l_row] = to_tf32(wv.z);
        Ws[buf][l_k0 + 3][l_row] = to_tf32(wv.w);
        __syncthreads();

        if (k0 + BK < kbeg + KS) { av = loadA(k0 + BK); wv = loadW(k0 + BK); }

#pragma unroll
        for (int kk = 0; kk < BK; kk += 8) {
            uint32_t afr[2][4];
#pragma unroll
            for (int mi = 0; mi < 2; mi++) {
                const int mb = wm * 32 + mi * 16;
                afr[mi][0] = __float_as_uint(As[buf][kk + tig    ][mb + grp    ]);
                afr[mi][1] = __float_as_uint(As[buf][kk + tig    ][mb + grp + 8]);
                afr[mi][2] = __float_as_uint(As[buf][kk + tig + 4][mb + grp    ]);
                afr[mi][3] = __float_as_uint(As[buf][kk + tig + 4][mb + grp + 8]);
            }
            uint32_t bfr[2][2];
#pragma unroll
            for (int ni = 0; ni < 2; ni++) {
                const int nb = wn * 16 + ni * 8;
                bfr[ni][0] = __float_as_uint(Ws[buf][kk + tig    ][nb + grp]);
                bfr[ni][1] = __float_as_uint(Ws[buf][kk + tig + 4][nb + grp]);
            }
#pragma unroll
            for (int mi = 0; mi < 2; mi++)
#pragma unroll
                for (int ni = 0; ni < 2; ni++)
                    mma_tf32(acc[mi][ni], afr[mi], bfr[ni]);
        }
        buf ^= 1;
    }

    // epilogue: write fp32 partials
#pragma unroll
    for (int mi = 0; mi < 2; mi++) {
#pragma unroll
        for (int ni = 0; ni < 2; ni++) {
            const int m = m0 + wm * 32 + mi * 16 + grp;
            const int n = n0 + wn * 16 + ni * 8 + tig * 2;
            float2 lo; lo.x = acc[mi][ni][0]; lo.y = acc[mi][ni][1];
            float2 hi; hi.x = acc[mi][ni][2]; hi.y = acc[mi][ni][3];
            *reinterpret_cast<float2*>(&P[(size_t)m       * NCOLS + n]) = lo;
            *reinterpret_cast<float2*>(&P[(size_t)(m + 8) * NCOLS + n]) = hi;
        }
    }
}

// ---------------------------------------------------------------------------
// Fused: y = P0 + P1 + q (q=[src|0|src_t]), then LayerNorm(y) -> g_H.
// One CTA per batch, 256 threads, 3 elements each (t, t+256, t+512).
// ---------------------------------------------------------------------------
__global__ __launch_bounds__(256) void lnred_kernel(
    const float* __restrict__ src,
    const float* __restrict__ src_t,
    const float* __restrict__ ln_w,
    const float* __restrict__ ln_b)
{
    const int b = blockIdx.x;
    const int t = threadIdx.x;
    const float* p0 = g_P + (size_t)b * MM;
    const float* p1 = g_P + (size_t)(BB + b) * MM;

    const float v0 = p0[t]       + p1[t]       + src[(size_t)b * DD + t];
    const float v1 = p0[t + 256] + p1[t + 256];
    const float v2 = p0[t + 512] + p1[t + 512] + src_t[(size_t)b * DD + t];

    float s = v0 + v1 + v2;
    float q = v0 * v0 + v1 * v1 + v2 * v2;
    __shared__ float sh[16];
#pragma unroll
    for (int o = 16; o; o >>= 1) {
        s += __shfl_xor_sync(0xffffffffu, s, o);
        q += __shfl_xor_sync(0xffffffffu, q, o);
    }
    const int wd = t >> 5, lane = t & 31;
    if (lane == 0) { sh[wd] = s; sh[8 + wd] = q; }
    __syncthreads();
    float st = 0.f, qt = 0.f;
#pragma unroll
    for (int i = 0; i < 8; i++) { st += sh[i]; qt += sh[8 + i]; }

    const float mu  = st * (1.f / 768.f);
    const float var = qt * (1.f / 768.f) - mu * mu;
    const float r   = rsqrtf(var + 1e-5f);
    float* hr = g_H + (size_t)b * MM;
    hr[t]       = (v0 - mu) * r * ln_w[t]       + ln_b[t];
    hr[t + 256] = (v1 - mu) * r * ln_w[t + 256] + ln_b[t + 256];
    hr[t + 512] = (v2 - mu) * r * ln_w[t + 512] + ln_b[t + 512];
}

// ---------------------------------------------------------------------------
// reduce1: g_X1 = relu(P0 + P1)
// ---------------------------------------------------------------------------
__global__ __launch_bounds__(256) void red_relu_kernel()
{
    const size_t i = ((size_t)blockIdx.x * 256 + threadIdx.x) * 4;
    const float4 a = *reinterpret_cast<const float4*>(g_P + i);
    const float4 b = *reinterpret_cast<const float4*>(g_P + (size_t)BB * MM + i);
    float4 v;
    v.x = fmaxf(a.x + b.x, 0.f); v.y = fmaxf(a.y + b.y, 0.f);
    v.z = fmaxf(a.z + b.z, 0.f); v.w = fmaxf(a.w + b.w, 0.f);
    *reinterpret_cast<float4*>(g_X1 + i) = v;
}

// ---------------------------------------------------------------------------
// reduce2: out = P0 + P1 + P2 + P3
// ---------------------------------------------------------------------------
__global__ __launch_bounds__(256) void red4_kernel(float* __restrict__ out)
{
    const size_t i = ((size_t)blockIdx.x * 256 + threadIdx.x) * 4;
    const float4 a = *reinterpret_cast<const float4*>(g_P + i);
    const float4 b = *reinterpret_cast<const float4*>(g_P + (size_t)1 * BB * DD + i);
    const float4 c = *reinterpret_cast<const float4*>(g_P + (size_t)2 * BB * DD + i);
    const float4 d = *reinterpret_cast<const float4*>(g_P + (size_t)3 * BB * DD + i);
    float4 v;
    v.x = a.x + b.x + c.x + d.x; v.y = a.y + b.y + c.y + d.y;
    v.z = a.z + b.z + c.z + d.z; v.w = a.w + b.w + c.w + d.w;
    *reinterpret_cast<float4*>(out + i) = v;
}

// ---------------------------------------------------------------------------
extern "C" void kernel_launch(void* const* d_in, const int* in_sizes, int n_in,
                              void* d_out, int out_size)
{
    const float* src         = (const float*)d_in[0];
    const float* src_t       = (const float*)d_in[1];
    const float* seq         = (const float*)d_in[2];
    const float* seq_t       = (const float*)d_in[3];
    const float* seq_e       = (const float*)d_in[4];
    const int*   mask        = (const int*)d_in[5];
    const float* shared_attn = (const float*)d_in[6];
    const float* fc_w        = (const float*)d_in[7];
    const float* ln_w        = (const float*)d_in[8];
    const float* ln_b        = (const float*)d_in[9];
    const float* w1          = (const float*)d_in[10];
    const float* w2          = (const float*)d_in[11];

    float* out      = (float*)d_out;          // (B, D)
    float* attn_out = out + (size_t)BB * DD;  // (B, N)

    // 1) attention (DRAM-bound, each key element read once)
    attn_kernel<<<BB, 192>>>(seq, seq_t, seq_e, mask, shared_attn, attn_out);

    // 2) partials of O @ fc_w.T   (split-K=2 -> 384 CTAs, tf32 mma)
    gemm_kernel<0, MM, 2, MM><<<dim3(BB / 64, MM / 64, 2), 256>>>(fc_w, src);

    // 3) fused reduce + residual q + LayerNorm -> g_H
    lnred_kernel<<<BB, 256>>>(src, src_t, ln_w, ln_b);

    // 4) partials of [H, src] @ W1.T   (split-K=2, tf32 mma)
    gemm_kernel<1, MM + DD, 2, MM><<<dim3(BB / 64, MM / 64, 2), 256>>>(w1, src);

    // 5) fused reduce + relu -> g_X1
    red_relu_kernel<<<(BB * MM) / (256 * 4), 256>>>();

    // 6) partials of X1 @ W2.T   (split-K=4 -> 256 CTAs, tf32 mma)
    gemm_kernel<2, MM, 4, DD><<<dim3(BB / 64, DD / 64, 4), 256>>>(w2, src);

    // 7) final reduce -> out
    red4_kernel<<<(BB * DD) / (256 * 4), 256>>>(out);
}